// round 3
// baseline (speedup 1.0000x reference)
#include <cuda_runtime.h>
#include <cuda_bf16.h>

#define HH 16
#define DD 64
#define BM 128
#define BN 64
#define KST 68   // padded smem row stride (words)

__device__ __forceinline__ unsigned f2tf(float f) {
    unsigned r; asm("cvt.rna.tf32.f32 %0, %1;" : "=r"(r) : "f"(f)); return r;
}
__device__ __forceinline__ float ex2(float x) {
    float r; asm("ex2.approx.f32 %0, %1;" : "=f"(r) : "f"(x)); return r;
}
__device__ __forceinline__ void mma8(float* c, const unsigned* a, unsigned b0, unsigned b1) {
    asm volatile("mma.sync.aligned.m16n8k8.row.col.f32.tf32.tf32.f32 "
        "{%0,%1,%2,%3}, {%4,%5,%6,%7}, {%8,%9}, {%0,%1,%2,%3};"
        : "+f"(c[0]), "+f"(c[1]), "+f"(c[2]), "+f"(c[3])
        : "r"(a[0]), "r"(a[1]), "r"(a[2]), "r"(a[3]), "r"(b0), "r"(b1));
}

// smem: one buffer; K tile in [0, 64*KST), V tile in [64*KST, 128*KST).
// Q staging (128 rows) uses the whole buffer before the main loop.
__shared__ unsigned smbuf[BM * KST];

__global__ __launch_bounds__(128, 2) void varlen_attn_mma(
    const float* __restrict__ Q,
    const float* __restrict__ K,
    const float* __restrict__ V,
    const int*   __restrict__ cu_q,
    const int*   __restrict__ cu_k,
    float*       __restrict__ O,
    int B)
{
    const int h = blockIdx.y;

    // ---- decode linear tile index -> (batch, tile) ----
    int t = blockIdx.x;
    int b, q0 = 0, lenq = 0;
    for (b = 0; b < B; b++) {
        q0 = cu_q[b]; lenq = cu_q[b + 1] - q0;
        int nt = (lenq + BM - 1) / BM;
        if (t < nt) break;
        t -= nt;
    }
    if (b >= B) return;
    const int k0   = cu_k[b];
    const int lenk = cu_k[b + 1] - k0;
    const int off  = lenk - lenq;

    const int tid  = threadIdx.x;
    const int warp = tid >> 5, lane = tid & 31;
    const int g    = lane >> 2, tg = lane & 3;

    const int rowbase = t * BM;
    // 4 query rows per thread: rb in {0,1} rowblocks, each with rows (+0, +8)
    int qrow[4];
    qrow[0] = rowbase + warp * 32 + g;
    qrow[1] = qrow[0] + 8;
    qrow[2] = qrow[0] + 16;
    qrow[3] = qrow[0] + 24;

    // ---- stage full Q tile (128 x 64 fp32) into smem ----
    {
        float* qsf = (float*)smbuf;
        #pragma unroll
        for (int i = 0; i < 16; i++) {
            int f = tid + i * 128;          // 0..2047
            int r = f >> 4, d4 = (f & 15) << 2;
            int qr = rowbase + r;
            float4 v = make_float4(0.f, 0.f, 0.f, 0.f);
            if (qr < lenq)
                v = *(const float4*)(Q + ((long)(q0 + qr) * HH + h) * DD + d4);
            *(float4*)&qsf[r * KST + d4] = v;
        }
    }
    __syncthreads();

    const float SC = 0.125f * 1.4426950408889634f;  // 1/sqrt(64) * log2(e)
    unsigned qa[2][8][4];
    {
        const float* qsf = (const float*)smbuf;
        #pragma unroll
        for (int rb = 0; rb < 2; rb++) {
            const int r0 = warp * 32 + rb * 16 + g, r1 = r0 + 8;
            #pragma unroll
            for (int k8 = 0; k8 < 8; k8++) {
                qa[rb][k8][0] = f2tf(qsf[r0 * KST + k8 * 8 + tg]     * SC);
                qa[rb][k8][1] = f2tf(qsf[r1 * KST + k8 * 8 + tg]     * SC);
                qa[rb][k8][2] = f2tf(qsf[r0 * KST + k8 * 8 + tg + 4] * SC);
                qa[rb][k8][3] = f2tf(qsf[r1 * KST + k8 * 8 + tg + 4] * SC);
            }
        }
    }
    __syncthreads();

    unsigned* const ksu = smbuf;
    unsigned* const vsu = smbuf + (BN * KST);

    float o[2][8][4];
    #pragma unroll
    for (int rb = 0; rb < 2; rb++)
        #pragma unroll
        for (int nt = 0; nt < 8; nt++)
            o[rb][nt][0] = o[rb][nt][1] = o[rb][nt][2] = o[rb][nt][3] = 0.f;
    float m[4] = {-1e30f, -1e30f, -1e30f, -1e30f};
    float l[4] = {0.f, 0.f, 0.f, 0.f};

    const int q_hi = min(rowbase + BM, lenq) - 1;
    const int kmax = min(lenk, q_hi + off + 1);

    for (int kt = 0; kt < kmax; kt += BN) {
        // ---- stage K/V tile (fp32 -> tf32 RNA once) ----
        #pragma unroll
        for (int i = 0; i < 8; i++) {
            int f = tid + i * 128;
            int r = f >> 4, d4 = (f & 15) << 2;
            int jg = kt + r;
            float4 kv = make_float4(0.f, 0.f, 0.f, 0.f), vv = kv;
            if (jg < lenk) {
                long base = ((long)(k0 + jg) * HH + h) * DD + d4;
                kv = *(const float4*)(K + base);
                vv = *(const float4*)(V + base);
            }
            *(uint4*)&ksu[r * KST + d4] = make_uint4(f2tf(kv.x), f2tf(kv.y), f2tf(kv.z), f2tf(kv.w));
            *(uint4*)&vsu[r * KST + d4] = make_uint4(f2tf(vv.x), f2tf(vv.y), f2tf(vv.z), f2tf(vv.w));
        }
        __syncthreads();

        // ---- S = Q K^T : shared B fragments feed both rowblocks ----
        float s[2][8][4];
        #pragma unroll
        for (int rb = 0; rb < 2; rb++)
            #pragma unroll
            for (int nt = 0; nt < 8; nt++)
                s[rb][nt][0] = s[rb][nt][1] = s[rb][nt][2] = s[rb][nt][3] = 0.f;
        #pragma unroll
        for (int k8 = 0; k8 < 8; k8++) {
            #pragma unroll
            for (int nt = 0; nt < 8; nt++) {
                unsigned b0 = ksu[(nt * 8 + g) * KST + k8 * 8 + tg];
                unsigned b1 = ksu[(nt * 8 + g) * KST + k8 * 8 + tg + 4];
                mma8(s[0][nt], qa[0][k8], b0, b1);
                mma8(s[1][nt], qa[1][k8], b0, b1);
            }
        }

        // ---- causal mask + row max (4 rows/thread) ----
        float tmax[4] = {-1e30f, -1e30f, -1e30f, -1e30f};
        #pragma unroll
        for (int rb = 0; rb < 2; rb++) {
            #pragma unroll
            for (int nt = 0; nt < 8; nt++) {
                int j0 = kt + nt * 8 + 2 * tg, j1 = j0 + 1;
                float* sv = s[rb][nt];
                sv[0] = (j0 <= qrow[rb * 2] + off)     ? sv[0] : -1e30f;
                sv[1] = (j1 <= qrow[rb * 2] + off)     ? sv[1] : -1e30f;
                sv[2] = (j0 <= qrow[rb * 2 + 1] + off) ? sv[2] : -1e30f;
                sv[3] = (j1 <= qrow[rb * 2 + 1] + off) ? sv[3] : -1e30f;
                tmax[rb * 2]     = fmaxf(tmax[rb * 2],     fmaxf(sv[0], sv[1]));
                tmax[rb * 2 + 1] = fmaxf(tmax[rb * 2 + 1], fmaxf(sv[2], sv[3]));
            }
        }
        #pragma unroll
        for (int r = 0; r < 4; r++) {
            tmax[r] = fmaxf(tmax[r], __shfl_xor_sync(0xffffffffu, tmax[r], 1));
            tmax[r] = fmaxf(tmax[r], __shfl_xor_sync(0xffffffffu, tmax[r], 2));
        }

        float mn[4], cr[4];
        #pragma unroll
        for (int r = 0; r < 4; r++) {
            mn[r] = fmaxf(m[r], tmax[r]);
            cr[r] = ex2(m[r] - mn[r]);
            m[r] = mn[r];
            l[r] *= cr[r];
        }

        // ---- p = exp2(s - m); rescale o ----
        #pragma unroll
        for (int rb = 0; rb < 2; rb++) {
            #pragma unroll
            for (int nt = 0; nt < 8; nt++) {
                float* sv = s[rb][nt];
                float p0 = ex2(sv[0] - mn[rb * 2]);
                float p1 = ex2(sv[1] - mn[rb * 2]);
                float p2 = ex2(sv[2] - mn[rb * 2 + 1]);
                float p3 = ex2(sv[3] - mn[rb * 2 + 1]);
                l[rb * 2]     += p0 + p1;
                l[rb * 2 + 1] += p2 + p3;
                sv[0] = p0; sv[1] = p1; sv[2] = p2; sv[3] = p3;
                o[rb][nt][0] *= cr[rb * 2];     o[rb][nt][1] *= cr[rb * 2];
                o[rb][nt][2] *= cr[rb * 2 + 1]; o[rb][nt][3] *= cr[rb * 2 + 1];
            }
        }

        // ---- O += P V  (key-permuted B; shared B fragments, 2 rowblocks) ----
        #pragma unroll
        for (int k8 = 0; k8 < 8; k8++) {
            unsigned pa0[4], pa1[4];
            pa0[0] = f2tf(s[0][k8][0]); pa0[1] = f2tf(s[0][k8][2]);
            pa0[2] = f2tf(s[0][k8][1]); pa0[3] = f2tf(s[0][k8][3]);
            pa1[0] = f2tf(s[1][k8][0]); pa1[1] = f2tf(s[1][k8][2]);
            pa1[2] = f2tf(s[1][k8][1]); pa1[3] = f2tf(s[1][k8][3]);
            const int kr0 = k8 * 8 + 2 * tg, kr1 = kr0 + 1;
            #pragma unroll
            for (int nt = 0; nt < 8; nt++) {
                unsigned b0 = vsu[kr0 * KST + nt * 8 + g];
                unsigned b1 = vsu[kr1 * KST + nt * 8 + g];
                mma8(o[0][nt], pa0, b0, b1);
                mma8(o[1][nt], pa1, b0, b1);
            }
        }
        __syncthreads();
    }

    // ---- epilogue: quad-reduce l, normalize, store 4 rows/thread ----
    #pragma unroll
    for (int r = 0; r < 4; r++) {
        l[r] += __shfl_xor_sync(0xffffffffu, l[r], 1);
        l[r] += __shfl_xor_sync(0xffffffffu, l[r], 2);
    }

    #pragma unroll
    for (int rb = 0; rb < 2; rb++) {
        #pragma unroll
        for (int half = 0; half < 2; half++) {
            int r = rb * 2 + half;
            if (qrow[r] < lenq) {
                float inv = 1.f / l[r];
                float* op = O + ((long)(q0 + qrow[r]) * HH + h) * DD;
                #pragma unroll
                for (int nt = 0; nt < 8; nt++)
                    *(float2*)(op + nt * 8 + 2 * tg) =
                        make_float2(o[rb][nt][2 * half] * inv, o[rb][nt][2 * half + 1] * inv);
            }
        }
    }
}

extern "C" void kernel_launch(void* const* d_in, const int* in_sizes, int n_in,
                              void* d_out, int out_size)
{
    const float* Q = (const float*)d_in[0];
    const float* K = (const float*)d_in[1];
    const float* V = (const float*)d_in[2];
    const int* cu_q = (const int*)d_in[3];
    const int* cu_k = (const int*)d_in[4];

    int B = in_sizes[3] - 1;
    int T = in_sizes[0] / (HH * DD);

    int max_tiles = (T + BM - 1) / BM + B;
    dim3 grid(max_tiles, HH);
    varlen_attn_mma<<<grid, 128>>>(Q, K, V, cu_q, cu_k, (float*)d_out, B);
}